// round 1
// baseline (speedup 1.0000x reference)
#include <cuda_runtime.h>
#include <math.h>

#define B_ 2
#define S_ 2048
#define E_ 1024
#define H_ 16
#define D_ 64
#define M_ (B_*S_)      // 4096 rows
#define K_ 1024

// Scratch (allocation-free rule: __device__ globals)
__device__ float g_q[B_*H_*S_*D_];      // [B,H,S,D]
__device__ float g_k[B_*H_*S_*D_];
__device__ float g_v[B_*H_*S_*D_];
__device__ float g_attn[M_*E_];         // [B*S, E]

// ---------------------------------------------------------------------------
// GEMM 64x64 tile, BK=16, 256 threads, 4x4 per thread.
// Writes QKV epilogue scattered into g_q/g_k/g_v with [B,H,S,D] layout.
// ---------------------------------------------------------------------------
__global__ __launch_bounds__(256) void gemm_qkv_kernel(
    const float* __restrict__ A,      // x  [4096, 1024]
    const float* __restrict__ W,      // Wqkv [1024, 3072]
    const float* __restrict__ bias)   // bqkv [3072]
{
    const int N = 3 * E_;
    __shared__ float As[16 * 64];
    __shared__ float Bs[16 * 64];
    const int tid = threadIdx.x;
    const int m0 = blockIdx.y * 64;
    const int n0 = blockIdx.x * 64;
    const int ty = tid >> 4, tx = tid & 15;

    float acc[4][4];
#pragma unroll
    for (int i = 0; i < 4; i++)
#pragma unroll
        for (int j = 0; j < 4; j++) acc[i][j] = 0.f;

    for (int k0 = 0; k0 < K_; k0 += 16) {
        // A tile 64x16 -> As[k][m]
        {
            int row = tid >> 2;
            int kq  = (tid & 3) * 4;
            float4 a4 = *(const float4*)(A + (size_t)(m0 + row) * K_ + k0 + kq);
            As[(kq + 0) * 64 + row] = a4.x;
            As[(kq + 1) * 64 + row] = a4.y;
            As[(kq + 2) * 64 + row] = a4.z;
            As[(kq + 3) * 64 + row] = a4.w;
        }
        // B tile 16x64 -> Bs[k][n]
        {
            int br = tid >> 4;
            int bc = (tid & 15) * 4;
            *(float4*)(Bs + br * 64 + bc) =
                *(const float4*)(W + (size_t)(k0 + br) * N + n0 + bc);
        }
        __syncthreads();
#pragma unroll
        for (int kk = 0; kk < 16; kk++) {
            float4 av = *(float4*)(As + kk * 64 + ty * 4);
            float4 bv = *(float4*)(Bs + kk * 64 + tx * 4);
            float a[4] = {av.x, av.y, av.z, av.w};
            float b[4] = {bv.x, bv.y, bv.z, bv.w};
#pragma unroll
            for (int i = 0; i < 4; i++)
#pragma unroll
                for (int j = 0; j < 4; j++) acc[i][j] += a[i] * b[j];
        }
        __syncthreads();
    }

#pragma unroll
    for (int i = 0; i < 4; i++) {
        int m = m0 + ty * 4 + i;
        int b = m >> 11;          // m / 2048
        int s = m & 2047;
#pragma unroll
        for (int j = 0; j < 4; j++) {
            int n = n0 + tx * 4 + j;
            float val = acc[i][j] + bias[n];
            int c = n >> 10;              // 0=q 1=k 2=v
            int h = (n >> 6) & 15;
            int d = n & 63;
            float* dst = (c == 0) ? g_q : (c == 1) ? g_k : g_v;
            dst[(((size_t)(b * H_ + h) * S_) + s) * D_ + d] = val;
        }
    }
}

// ---------------------------------------------------------------------------
// Output projection GEMM: g_attn [4096,1024] @ Wout [1024,1024] + bout
// ---------------------------------------------------------------------------
__global__ __launch_bounds__(256) void gemm_out_kernel(
    const float* __restrict__ W,      // Wout [1024,1024]
    const float* __restrict__ bias,   // bout
    float* __restrict__ Cout)         // [4096,1024]
{
    const int N = E_;
    const float* A = g_attn;
    __shared__ float As[16 * 64];
    __shared__ float Bs[16 * 64];
    const int tid = threadIdx.x;
    const int m0 = blockIdx.y * 64;
    const int n0 = blockIdx.x * 64;
    const int ty = tid >> 4, tx = tid & 15;

    float acc[4][4];
#pragma unroll
    for (int i = 0; i < 4; i++)
#pragma unroll
        for (int j = 0; j < 4; j++) acc[i][j] = 0.f;

    for (int k0 = 0; k0 < K_; k0 += 16) {
        {
            int row = tid >> 2;
            int kq  = (tid & 3) * 4;
            float4 a4 = *(const float4*)(A + (size_t)(m0 + row) * K_ + k0 + kq);
            As[(kq + 0) * 64 + row] = a4.x;
            As[(kq + 1) * 64 + row] = a4.y;
            As[(kq + 2) * 64 + row] = a4.z;
            As[(kq + 3) * 64 + row] = a4.w;
        }
        {
            int br = tid >> 4;
            int bc = (tid & 15) * 4;
            *(float4*)(Bs + br * 64 + bc) =
                *(const float4*)(W + (size_t)(k0 + br) * N + n0 + bc);
        }
        __syncthreads();
#pragma unroll
        for (int kk = 0; kk < 16; kk++) {
            float4 av = *(float4*)(As + kk * 64 + ty * 4);
            float4 bv = *(float4*)(Bs + kk * 64 + tx * 4);
            float a[4] = {av.x, av.y, av.z, av.w};
            float b[4] = {bv.x, bv.y, bv.z, bv.w};
#pragma unroll
            for (int i = 0; i < 4; i++)
#pragma unroll
                for (int j = 0; j < 4; j++) acc[i][j] += a[i] * b[j];
        }
        __syncthreads();
    }

#pragma unroll
    for (int i = 0; i < 4; i++) {
        int m = m0 + ty * 4 + i;
#pragma unroll
        for (int j = 0; j < 4; j++) {
            int n = n0 + tx * 4 + j;
            Cout[(size_t)m * N + n] = acc[i][j] + bias[n];
        }
    }
}

// ---------------------------------------------------------------------------
// Flash attention, causal. One block per (q-tile of 64 rows, head, batch).
// 256 threads. Dynamic smem: Q[64*64], K[64*64], V[64*64], S[64*65].
// ---------------------------------------------------------------------------
#define SS_LD 65
#define ATTN_SMEM ((64*64*3 + 64*SS_LD) * (int)sizeof(float))

__global__ __launch_bounds__(256) void attn_kernel()
{
    extern __shared__ float sm[];
    float* Qs = sm;                 // [64][64]
    float* Ks = sm + 64 * 64;       // [64][64]
    float* Vs = sm + 2 * 64 * 64;   // [64][64]
    float* Ss = sm + 3 * 64 * 64;   // [64][65]

    const int tid = threadIdx.x;
    const int qt = blockIdx.x;      // 0..31
    const int h  = blockIdx.y;
    const int b  = blockIdx.z;

    const size_t base = (size_t)(b * H_ + h) * S_ * D_;
    const float* qbase = g_q + base;
    const float* kbase = g_k + base;
    const float* vbase = g_v + base;

    const float scale = 0.125f;     // 1/sqrt(64)

    // Load Q tile (pre-scaled)
#pragma unroll
    for (int it = 0; it < 4; it++) {
        int f4  = tid + it * 256;
        int row = f4 >> 4;
        int c4  = (f4 & 15) * 4;
        float4 v = *(const float4*)(qbase + (size_t)(qt * 64 + row) * 64 + c4);
        v.x *= scale; v.y *= scale; v.z *= scale; v.w *= scale;
        *(float4*)(Qs + row * 64 + c4) = v;
    }

    const int row = tid >> 2;       // 0..63 (softmax/PV layout)
    const int sub = tid & 3;        // owns cols sub*16..sub*16+15
    const int ty = tid >> 4, tx = tid & 15;  // QK layout

    float m_i = -1e30f, l_i = 0.f;
    float o[16];
#pragma unroll
    for (int i = 0; i < 16; i++) o[i] = 0.f;

    for (int kt = 0; kt <= qt; kt++) {
        // Load K, V tiles
#pragma unroll
        for (int it = 0; it < 4; it++) {
            int f4 = tid + it * 256;
            int r  = f4 >> 4;
            int c4 = (f4 & 15) * 4;
            *(float4*)(Ks + r * 64 + c4) =
                *(const float4*)(kbase + (size_t)(kt * 64 + r) * 64 + c4);
            *(float4*)(Vs + r * 64 + c4) =
                *(const float4*)(vbase + (size_t)(kt * 64 + r) * 64 + c4);
        }
        __syncthreads();

        // S = Q K^T  (4x4 per thread)
        float acc[4][4];
#pragma unroll
        for (int i = 0; i < 4; i++)
#pragma unroll
            for (int j = 0; j < 4; j++) acc[i][j] = 0.f;

#pragma unroll
        for (int d = 0; d < 64; d += 4) {
            float4 qa[4], kb[4];
#pragma unroll
            for (int i = 0; i < 4; i++) qa[i] = *(float4*)(Qs + (ty * 4 + i) * 64 + d);
#pragma unroll
            for (int j = 0; j < 4; j++) kb[j] = *(float4*)(Ks + (tx * 4 + j) * 64 + d);
#pragma unroll
            for (int i = 0; i < 4; i++)
#pragma unroll
                for (int j = 0; j < 4; j++) {
                    acc[i][j] += qa[i].x * kb[j].x + qa[i].y * kb[j].y
                               + qa[i].z * kb[j].z + qa[i].w * kb[j].w;
                }
        }
        const bool diag = (kt == qt);
#pragma unroll
        for (int i = 0; i < 4; i++)
#pragma unroll
            for (int j = 0; j < 4; j++) {
                float v = acc[i][j];
                if (diag && (tx * 4 + j > ty * 4 + i)) v = -1e30f;
                Ss[(ty * 4 + i) * SS_LD + tx * 4 + j] = v;
            }
        __syncthreads();

        // Online softmax (4 threads per row)
        float tmax = -1e30f;
#pragma unroll
        for (int j = 0; j < 16; j++)
            tmax = fmaxf(tmax, Ss[row * SS_LD + sub * 16 + j]);
        tmax = fmaxf(tmax, __shfl_xor_sync(0xffffffffu, tmax, 1));
        tmax = fmaxf(tmax, __shfl_xor_sync(0xffffffffu, tmax, 2));
        float m_new = fmaxf(m_i, tmax);
        float corr  = __expf(m_i - m_new);
        float psum  = 0.f;
#pragma unroll
        for (int j = 0; j < 16; j++) {
            float p = __expf(Ss[row * SS_LD + sub * 16 + j] - m_new);
            Ss[row * SS_LD + sub * 16 + j] = p;
            psum += p;
        }
        psum += __shfl_xor_sync(0xffffffffu, psum, 1);
        psum += __shfl_xor_sync(0xffffffffu, psum, 2);
        l_i = l_i * corr + psum;
        m_i = m_new;
#pragma unroll
        for (int i = 0; i < 16; i++) o[i] *= corr;
        __syncwarp();

        // O += P @ V  (each thread: 16 dims of its row)
#pragma unroll 8
        for (int j = 0; j < 64; j++) {
            float p = Ss[row * SS_LD + j];
            float4 v0 = *(float4*)(Vs + j * 64 + sub * 16 + 0);
            float4 v1 = *(float4*)(Vs + j * 64 + sub * 16 + 4);
            float4 v2 = *(float4*)(Vs + j * 64 + sub * 16 + 8);
            float4 v3 = *(float4*)(Vs + j * 64 + sub * 16 + 12);
            o[0]  += p * v0.x; o[1]  += p * v0.y; o[2]  += p * v0.z; o[3]  += p * v0.w;
            o[4]  += p * v1.x; o[5]  += p * v1.y; o[6]  += p * v1.z; o[7]  += p * v1.w;
            o[8]  += p * v2.x; o[9]  += p * v2.y; o[10] += p * v2.z; o[11] += p * v2.w;
            o[12] += p * v3.x; o[13] += p * v3.y; o[14] += p * v3.z; o[15] += p * v3.w;
        }
        __syncthreads();
    }

    const float inv = 1.f / l_i;
    float* op = g_attn + (size_t)(b * S_ + qt * 64 + row) * E_ + h * 64 + sub * 16;
#pragma unroll
    for (int q4 = 0; q4 < 4; q4++) {
        float4 v;
        v.x = o[q4 * 4 + 0] * inv;
        v.y = o[q4 * 4 + 1] * inv;
        v.z = o[q4 * 4 + 2] * inv;
        v.w = o[q4 * 4 + 3] * inv;
        *(float4*)(op + q4 * 4) = v;
    }
}

// ---------------------------------------------------------------------------
extern "C" void kernel_launch(void* const* d_in, const int* in_sizes, int n_in,
                              void* d_out, int out_size)
{
    const float* x    = (const float*)d_in[0];
    const float* Wqkv = (const float*)d_in[1];
    const float* bqkv = (const float*)d_in[2];
    const float* Wout = (const float*)d_in[3];
    const float* bout = (const float*)d_in[4];
    float* out = (float*)d_out;

    static bool attr_set = false;
    if (!attr_set) {
        cudaFuncSetAttribute(attn_kernel,
                             cudaFuncAttributeMaxDynamicSharedMemorySize,
                             ATTN_SMEM);
        attr_set = true;
    }

    dim3 blk(256);
    dim3 g1(3 * E_ / 64, M_ / 64);     // (48, 64)
    gemm_qkv_kernel<<<g1, blk>>>(x, Wqkv, bqkv);

    dim3 g2(S_ / 64, H_, B_);          // (32, 16, 2)
    attn_kernel<<<g2, blk, ATTN_SMEM>>>();

    dim3 g3(E_ / 64, M_ / 64);         // (16, 64)
    gemm_out_kernel<<<g3, blk>>>(Wout, bout, out);
}

// round 14
// speedup vs baseline: 3.9704x; 3.9704x over previous
#include <cuda_runtime.h>
#include <cuda_bf16.h>
#include <cstdint>
#include <math.h>

#define B_ 2
#define S_ 2048
#define E_ 1024
#define H_ 16
#define D_ 64
#define M_ (B_*S_)      // 4096
#define K_ 1024
#define N_QKV (3*E_)    // 3072

// ---------------------------------------------------------------------------
// Scratch (__device__ globals; allocation-free rule)
// ---------------------------------------------------------------------------
__device__ __nv_bfloat16 g_qh[B_*H_*S_*D_], g_ql[B_*H_*S_*D_];  // [B,H,S,64]
__device__ __nv_bfloat16 g_kh[B_*H_*S_*D_], g_kl[B_*H_*S_*D_];
__device__ __nv_bfloat16 g_vh[B_*H_*S_*D_], g_vl[B_*H_*S_*D_];
__device__ __nv_bfloat16 g_ah[M_*E_], g_al[M_*E_];              // attn out split [B*S, E]

__device__ __nv_bfloat16 g_xh[M_*K_],  g_xl[M_*K_];             // x split
__device__ __nv_bfloat16 g_wqh[N_QKV*K_], g_wql[N_QKV*K_];      // Wqkv^T split [3072][1024]
__device__ __nv_bfloat16 g_woh[E_*K_], g_wol[E_*K_];            // Wout^T split [1024][1024]

// ---------------------------------------------------------------------------
// mma.sync m16n8k16 bf16 (HMMA path — legal on plain sm_103 PTX target)
// ---------------------------------------------------------------------------
__device__ __forceinline__ void mma16816(float* c, const uint32_t* a, const uint32_t* b)
{
    asm volatile(
        "mma.sync.aligned.m16n8k16.row.col.f32.bf16.bf16.f32 "
        "{%0,%1,%2,%3}, {%4,%5,%6,%7}, {%8,%9}, {%0,%1,%2,%3};"
        : "+f"(c[0]), "+f"(c[1]), "+f"(c[2]), "+f"(c[3])
        : "r"(a[0]), "r"(a[1]), "r"(a[2]), "r"(a[3]), "r"(b[0]), "r"(b[1]));
}

// Split two fp32 into packed bf16 hi-pair and bf16 lo(residual)-pair.
__device__ __forceinline__ void split2(float v0, float v1, uint32_t& hp, uint32_t& lp)
{
    __nv_bfloat16 h0 = __float2bfloat16_rn(v0), h1 = __float2bfloat16_rn(v1);
    float r0 = v0 - __bfloat162float(h0);
    float r1 = v1 - __bfloat162float(h1);
    __nv_bfloat16 l0 = __float2bfloat16_rn(r0), l1 = __float2bfloat16_rn(r1);
    hp = ((uint32_t)__bfloat16_as_ushort(h1) << 16) | (uint32_t)__bfloat16_as_ushort(h0);
    lp = ((uint32_t)__bfloat16_as_ushort(l1) << 16) | (uint32_t)__bfloat16_as_ushort(l0);
}

// ---------------------------------------------------------------------------
// Prep kernels (fp32 -> split bf16; W also transposed)
// ---------------------------------------------------------------------------
__global__ void split_kernel(const float* __restrict__ src,
                             __nv_bfloat16* __restrict__ dh,
                             __nv_bfloat16* __restrict__ dl, int n)
{
    int i = blockIdx.x * blockDim.x + threadIdx.x;
    if (i >= n) return;
    float v = src[i];
    __nv_bfloat16 h = __float2bfloat16_rn(v);
    float r = v - __bfloat162float(h);
    dh[i] = h;
    dl[i] = __float2bfloat16_rn(r);
}

__global__ void transpose_split_kernel(const float* __restrict__ src,
                                       __nv_bfloat16* __restrict__ dh,
                                       __nv_bfloat16* __restrict__ dl,
                                       int Kdim, int Ndim)
{
    int i = blockIdx.x * blockDim.x + threadIdx.x;
    if (i >= Kdim * Ndim) return;
    int k = i / Ndim, n = i - k * Ndim;
    float v = src[i];
    __nv_bfloat16 h = __float2bfloat16_rn(v);
    float r = v - __bfloat162float(h);
    dh[(size_t)n * Kdim + k] = h;
    dl[(size_t)n * Kdim + k] = __float2bfloat16_rn(r);
}

// ---------------------------------------------------------------------------
// Split-bf16 HMMA GEMM: C[M_ x NTOT] = A[M_,1024] @ B[NTOT,1024]^T + bias
// 256 thr / 8 warps (2x4), warp tile m64 n32, BK=32, smem stride 40.
// MODE 0: qkv epilogue (scale q by 0.125, write split to g_q*/g_k*/g_v*)
// MODE 1: plain fp32 out.
// ---------------------------------------------------------------------------
#define GSTR 40
#define GEMM_SMEM (4 * 128 * GSTR * 2)   // 40960 B

template<int MODE, int NTOT>
__global__ __launch_bounds__(256) void gemm_mma_kernel(
    const __nv_bfloat16* __restrict__ Ah, const __nv_bfloat16* __restrict__ Al,
    const __nv_bfloat16* __restrict__ Bh, const __nv_bfloat16* __restrict__ Bl,
    const float* __restrict__ bias, float* __restrict__ Cout)
{
    extern __shared__ __nv_bfloat16 smg[];
    __nv_bfloat16* Ash = smg;
    __nv_bfloat16* Asl = smg + 128 * GSTR;
    __nv_bfloat16* Bsh = smg + 2 * 128 * GSTR;
    __nv_bfloat16* Bsl = smg + 3 * 128 * GSTR;

    const int tid = threadIdx.x;
    const int wid = tid >> 5, lane = tid & 31;
    const int g = lane >> 2, c = lane & 3;
    const int wm = (wid & 1) * 64, wn = (wid >> 1) * 32;
    const int m0 = blockIdx.y * 128, n0 = blockIdx.x * 128;

    float acc[4][4][4];
#pragma unroll
    for (int i = 0; i < 4; i++)
#pragma unroll
        for (int j = 0; j < 4; j++)
#pragma unroll
            for (int e = 0; e < 4; e++) acc[i][j][e] = 0.f;

    for (int k0 = 0; k0 < K_; k0 += 32) {
#pragma unroll
        for (int it = 0; it < 2; it++) {
            int f = tid + it * 256;
            int row = f >> 2, q = (f & 3) * 8;
            *(uint4*)(Ash + row * GSTR + q) =
                *(const uint4*)(Ah + (size_t)(m0 + row) * K_ + k0 + q);
            *(uint4*)(Asl + row * GSTR + q) =
                *(const uint4*)(Al + (size_t)(m0 + row) * K_ + k0 + q);
            *(uint4*)(Bsh + row * GSTR + q) =
                *(const uint4*)(Bh + (size_t)(n0 + row) * K_ + k0 + q);
            *(uint4*)(Bsl + row * GSTR + q) =
                *(const uint4*)(Bl + (size_t)(n0 + row) * K_ + k0 + q);
        }
        __syncthreads();

#pragma unroll
        for (int s = 0; s < 2; s++) {
            uint32_t ah[4][4], al[4][4], bh[4][2], bl[4][2];
#pragma unroll
            for (int i = 0; i < 4; i++) {
                const __nv_bfloat16* p = Ash + (wm + i * 16 + g) * GSTR + s * 16 + 2 * c;
                ah[i][0] = *(const uint32_t*)p;
                ah[i][1] = *(const uint32_t*)(p + 8 * GSTR);
                ah[i][2] = *(const uint32_t*)(p + 8);
                ah[i][3] = *(const uint32_t*)(p + 8 * GSTR + 8);
                const __nv_bfloat16* q2 = Asl + (wm + i * 16 + g) * GSTR + s * 16 + 2 * c;
                al[i][0] = *(const uint32_t*)q2;
                al[i][1] = *(const uint32_t*)(q2 + 8 * GSTR);
                al[i][2] = *(const uint32_t*)(q2 + 8);
                al[i][3] = *(const uint32_t*)(q2 + 8 * GSTR + 8);
            }
#pragma unroll
            for (int j = 0; j < 4; j++) {
                const __nv_bfloat16* p = Bsh + (wn + j * 8 + g) * GSTR + s * 16 + 2 * c;
                bh[j][0] = *(const uint32_t*)p;
                bh[j][1] = *(const uint32_t*)(p + 8);
                const __nv_bfloat16* q2 = Bsl + (wn + j * 8 + g) * GSTR + s * 16 + 2 * c;
                bl[j][0] = *(const uint32_t*)q2;
                bl[j][1] = *(const uint32_t*)(q2 + 8);
            }
#pragma unroll
            for (int i = 0; i < 4; i++)
#pragma unroll
                for (int j = 0; j < 4; j++) {
                    mma16816(acc[i][j], ah[i], bh[j]);
                    mma16816(acc[i][j], ah[i], bl[j]);
                    mma16816(acc[i][j], al[i], bh[j]);
                }
        }
        __syncthreads();
    }

    // Epilogue
#pragma unroll
    for (int i = 0; i < 4; i++) {
#pragma unroll
        for (int j = 0; j < 4; j++) {
            int gcol = n0 + wn + j * 8 + 2 * c;
            int r0 = m0 + wm + i * 16 + g;
            float b0 = bias[gcol], b1 = bias[gcol + 1];
            if (MODE == 0) {
                int cc = gcol >> 10, hh = (gcol >> 6) & 15, d = gcol & 63;
                float sc = (cc == 0) ? 0.125f : 1.0f;
                __nv_bfloat16* dh = (cc == 0) ? g_qh : (cc == 1) ? g_kh : g_vh;
                __nv_bfloat16* dl = (cc == 0) ? g_ql : (cc == 1) ? g_kl : g_vl;
#pragma unroll
                for (int half = 0; half < 2; half++) {
                    int r = r0 + half * 8;
                    int bb = r >> 11, ss = r & 2047;
                    size_t idx = (((size_t)(bb * H_ + hh)) * S_ + ss) * (size_t)D_ + d;
                    uint32_t hp, lp;
                    split2((acc[i][j][2 * half] + b0) * sc,
                           (acc[i][j][2 * half + 1] + b1) * sc, hp, lp);
                    *(uint32_t*)(dh + idx) = hp;
                    *(uint32_t*)(dl + idx) = lp;
                }
            } else {
                float2 v0 = make_float2(acc[i][j][0] + b0, acc[i][j][1] + b1);
                float2 v1 = make_float2(acc[i][j][2] + b0, acc[i][j][3] + b1);
                *(float2*)(Cout + (size_t)r0 * NTOT + gcol) = v0;
                *(float2*)(Cout + (size_t)(r0 + 8) * NTOT + gcol) = v1;
            }
        }
    }
}

// ---------------------------------------------------------------------------
// Flash attention on HMMA, causal, split-bf16 QK^T and PV.
// Block: 128 q-rows, 8 warps (m16 each), K/V tiles of 64 keys in smem.
// ---------------------------------------------------------------------------
#define SK 72
#define ATTN_SMEM (4 * 64 * SK * 2)      // 36864 B

__global__ __launch_bounds__(256) void attn_mma_kernel()
{
    extern __shared__ __nv_bfloat16 sma[];
    __nv_bfloat16* Ksh = sma;
    __nv_bfloat16* Ksl = sma + 64 * SK;
    __nv_bfloat16* Vsh = sma + 2 * 64 * SK;
    __nv_bfloat16* Vsl = sma + 3 * 64 * SK;

    const int tid = threadIdx.x;
    const int wid = tid >> 5, lane = tid & 31;
    const int g = lane >> 2, c = lane & 3;
    const int qt = blockIdx.x, h = blockIdx.y, b = blockIdx.z;

    const size_t base = (size_t)(b * H_ + h) * S_ * D_;
    const int wrow = qt * 128 + wid * 16;        // warp's first q row (in-sequence)

    // Q A-frags (hi/lo), 4 ksteps over 64 dims. q pre-scaled by 0.125 at QKV epilogue.
    uint32_t qh[4][4], ql[4][4];
#pragma unroll
    for (int s = 0; s < 4; s++) {
        const __nv_bfloat16* p = g_qh + base + (size_t)(wrow + g) * D_ + s * 16 + 2 * c;
        qh[s][0] = *(const uint32_t*)p;
        qh[s][1] = *(const uint32_t*)(p + 8 * D_);
        qh[s][2] = *(const uint32_t*)(p + 8);
        qh[s][3] = *(const uint32_t*)(p + 8 * D_ + 8);
        const __nv_bfloat16* q2 = g_ql + base + (size_t)(wrow + g) * D_ + s * 16 + 2 * c;
        ql[s][0] = *(const uint32_t*)q2;
        ql[s][1] = *(const uint32_t*)(q2 + 8 * D_);
        ql[s][2] = *(const uint32_t*)(q2 + 8);
        ql[s][3] = *(const uint32_t*)(q2 + 8 * D_ + 8);
    }

    float o[8][4];
#pragma unroll
    for (int j = 0; j < 8; j++)
#pragma unroll
        for (int e = 0; e < 4; e++) o[j][e] = 0.f;
    float mi0 = -1e30f, mi1 = -1e30f, li0 = 0.f, li1 = 0.f;

    const int r0 = wrow + g, r1 = r0 + 8;
    const int ktmax = 2 * qt + 1;

    for (int kt = 0; kt <= ktmax; kt++) {
        // Load K/V tiles (64 x 64, hi/lo)
#pragma unroll
        for (int it = 0; it < 2; it++) {
            int f = tid + it * 256;
            int row = f >> 3, q = (f & 7) * 8;
            size_t gi = base + (size_t)(kt * 64 + row) * D_ + q;
            *(uint4*)(Ksh + row * SK + q) = *(const uint4*)(g_kh + gi);
            *(uint4*)(Ksl + row * SK + q) = *(const uint4*)(g_kl + gi);
            *(uint4*)(Vsh + row * SK + q) = *(const uint4*)(g_vh + gi);
            *(uint4*)(Vsl + row * SK + q) = *(const uint4*)(g_vl + gi);
        }
        __syncthreads();

        if (kt * 64 <= wrow + 15) {   // tile not fully masked for this warp
            // S = Q K^T (split 3-product)
            float St[8][4];
#pragma unroll
            for (int j = 0; j < 8; j++)
#pragma unroll
                for (int e = 0; e < 4; e++) St[j][e] = 0.f;

#pragma unroll
            for (int s = 0; s < 4; s++) {
#pragma unroll
                for (int j = 0; j < 8; j++) {
                    const __nv_bfloat16* p = Ksh + (j * 8 + g) * SK + s * 16 + 2 * c;
                    uint32_t bh[2] = { *(const uint32_t*)p, *(const uint32_t*)(p + 8) };
                    const __nv_bfloat16* q2 = Ksl + (j * 8 + g) * SK + s * 16 + 2 * c;
                    uint32_t bl[2] = { *(const uint32_t*)q2, *(const uint32_t*)(q2 + 8) };
                    mma16816(St[j], qh[s], bh);
                    mma16816(St[j], qh[s], bl);
                    mma16816(St[j], ql[s], bh);
                }
            }

            // Causal mask
            if (kt * 64 + 63 > wrow) {
#pragma unroll
                for (int j = 0; j < 8; j++)
#pragma unroll
                    for (int e = 0; e < 2; e++) {
                        int col = kt * 64 + j * 8 + 2 * c + e;
                        if (col > r0) St[j][e]     = -1e30f;
                        if (col > r1) St[j][e + 2] = -1e30f;
                    }
            }

            // Online softmax (rows r0, r1; 4 lanes per row)
            float tm0 = -1e30f, tm1 = -1e30f;
#pragma unroll
            for (int j = 0; j < 8; j++) {
                tm0 = fmaxf(tm0, fmaxf(St[j][0], St[j][1]));
                tm1 = fmaxf(tm1, fmaxf(St[j][2], St[j][3]));
            }
            tm0 = fmaxf(tm0, __shfl_xor_sync(0xffffffffu, tm0, 1));
            tm0 = fmaxf(tm0, __shfl_xor_sync(0xffffffffu, tm0, 2));
            tm1 = fmaxf(tm1, __shfl_xor_sync(0xffffffffu, tm1, 1));
            tm1 = fmaxf(tm1, __shfl_xor_sync(0xffffffffu, tm1, 2));
            float mn0 = fmaxf(mi0, tm0), mn1 = fmaxf(mi1, tm1);
            float corr0 = __expf(mi0 - mn0), corr1 = __expf(mi1 - mn1);
            mi0 = mn0; mi1 = mn1;

            float ps0 = 0.f, ps1 = 0.f;
#pragma unroll
            for (int j = 0; j < 8; j++) {
                St[j][0] = __expf(St[j][0] - mn0); ps0 += St[j][0];
                St[j][1] = __expf(St[j][1] - mn0); ps0 += St[j][1];
                St[j][2] = __expf(St[j][2] - mn1); ps1 += St[j][2];
                St[j][3] = __expf(St[j][3] - mn1); ps1 += St[j][3];
            }
            ps0 += __shfl_xor_sync(0xffffffffu, ps0, 1);
            ps0 += __shfl_xor_sync(0xffffffffu, ps0, 2);
            ps1 += __shfl_xor_sync(0xffffffffu, ps1, 1);
            ps1 += __shfl_xor_sync(0xffffffffu, ps1, 2);
            li0 = li0 * corr0 + ps0;
            li1 = li1 * corr1 + ps1;
#pragma unroll
            for (int j = 0; j < 8; j++) {
                o[j][0] *= corr0; o[j][1] *= corr0;
                o[j][2] *= corr1; o[j][3] *= corr1;
            }

            // P -> A-frags (hi/lo) via the C->A frag identity
            uint32_t ph[4][4], pl[4][4];
#pragma unroll
            for (int s = 0; s < 4; s++) {
                split2(St[2 * s][0],     St[2 * s][1],     ph[s][0], pl[s][0]);
                split2(St[2 * s][2],     St[2 * s][3],     ph[s][1], pl[s][1]);
                split2(St[2 * s + 1][0], St[2 * s + 1][1], ph[s][2], pl[s][2]);
                split2(St[2 * s + 1][2], St[2 * s + 1][3], ph[s][3], pl[s][3]);
            }

            // O += P V (split 3-product). V B-frags built from [key][dim] smem.
#pragma unroll
            for (int s = 0; s < 4; s++) {
                int k0 = s * 16 + 2 * c;
#pragma unroll
                for (int j = 0; j < 8; j++) {
                    int n = j * 8 + g;
                    uint32_t bh[2], bl[2];
                    bh[0] = (uint32_t)__bfloat16_as_ushort(Vsh[k0 * SK + n]) |
                            ((uint32_t)__bfloat16_as_ushort(Vsh[(k0 + 1) * SK + n]) << 16);
                    bh[1] = (uint32_t)__bfloat16_as_ushort(Vsh[(k0 + 8) * SK + n]) |
                            ((uint32_t)__bfloat16_as_ushort(Vsh[(k0 + 9) * SK + n]) << 16);
                    bl[0] = (uint32_t)__bfloat16_as_ushort(Vsl[k0 * SK + n]) |
                            ((uint32_t)__bfloat16_as_ushort(Vsl[(k0 + 1) * SK + n]) << 16);
                    bl[1] = (uint32_t)__bfloat16_as_ushort(Vsl[(k0 + 8) * SK + n]) |
                            ((uint32_t)__bfloat16_as_ushort(Vsl[(k0 + 9) * SK + n]) << 16);
                    mma16816(o[j], ph[s], bh);
                    mma16816(o[j], ph[s], bl);
                    mma16816(o[j], pl[s], bh);
                }
            }
        }
        __syncthreads();
    }

    // Epilogue: O /= l, write split bf16 to g_ah/g_al [B*S, 1024]
    float inv0 = 1.f / li0, inv1 = 1.f / li1;
#pragma unroll
    for (int j = 0; j < 8; j++) {
        int col = h * 64 + j * 8 + 2 * c;
        size_t row0 = (size_t)(b * S_ + wrow + g);
        uint32_t hp, lp;
        split2(o[j][0] * inv0, o[j][1] * inv0, hp, lp);
        *(uint32_t*)(g_ah + row0 * E_ + col) = hp;
        *(uint32_t*)(g_al + row0 * E_ + col) = lp;
        split2(o[j][2] * inv1, o[j][3] * inv1, hp, lp);
        *(uint32_t*)(g_ah + (row0 + 8) * E_ + col) = hp;
        *(uint32_t*)(g_al + (row0 + 8) * E_ + col) = lp;
    }
}

// ---------------------------------------------------------------------------
extern "C" void kernel_launch(void* const* d_in, const int* in_sizes, int n_in,
                              void* d_out, int out_size)
{
    const float* x    = (const float*)d_in[0];
    const float* Wqkv = (const float*)d_in[1];
    const float* bqkv = (const float*)d_in[2];
    const float* Wout = (const float*)d_in[3];
    const float* bout = (const float*)d_in[4];
    float* out = (float*)d_out;

    static bool attr_set = false;
    if (!attr_set) {
        cudaFuncSetAttribute(attn_mma_kernel,
                             cudaFuncAttributeMaxDynamicSharedMemorySize, ATTN_SMEM);
        cudaFuncSetAttribute(gemm_mma_kernel<0, N_QKV>,
                             cudaFuncAttributeMaxDynamicSharedMemorySize, GEMM_SMEM);
        cudaFuncSetAttribute(gemm_mma_kernel<1, E_>,
                             cudaFuncAttributeMaxDynamicSharedMemorySize, GEMM_SMEM);
        attr_set = true;
    }

    __nv_bfloat16 *xh, *xl, *wqh, *wql, *woh, *wol, *ah, *al;
    cudaGetSymbolAddress((void**)&xh,  g_xh);
    cudaGetSymbolAddress((void**)&xl,  g_xl);
    cudaGetSymbolAddress((void**)&wqh, g_wqh);
    cudaGetSymbolAddress((void**)&wql, g_wql);
    cudaGetSymbolAddress((void**)&woh, g_woh);
    cudaGetSymbolAddress((void**)&wol, g_wol);
    cudaGetSymbolAddress((void**)&ah,  g_ah);
    cudaGetSymbolAddress((void**)&al,  g_al);

    // Prep: splits + transposed weight splits
    split_kernel<<<(M_*K_ + 255) / 256, 256>>>(x, xh, xl, M_*K_);
    transpose_split_kernel<<<(K_*N_QKV + 255) / 256, 256>>>(Wqkv, wqh, wql, K_, N_QKV);
    transpose_split_kernel<<<(K_*E_ + 255) / 256, 256>>>(Wout, woh, wol, K_, E_);

    // QKV projection (HMMA, split epilogue into q/k/v)
    {
        dim3 grd(N_QKV / 128, M_ / 128);   // (24, 32)
        gemm_mma_kernel<0, N_QKV><<<grd, 256, GEMM_SMEM>>>(xh, xl, wqh, wql, bqkv, nullptr);
    }

    // Attention (HMMA flash)
    {
        dim3 grd(S_ / 128, H_, B_);        // (16, 16, 2)
        attn_mma_kernel<<<grd, 256, ATTN_SMEM>>>();
    }

    // Output projection (HMMA)
    {
        dim3 grd(E_ / 128, M_ / 128);      // (8, 32)
        gemm_mma_kernel<1, E_><<<grd, 256, GEMM_SMEM>>>(ah, al, woh, wol, bout, out);
    }
}